// round 12
// baseline (speedup 1.0000x reference)
#include <cuda_runtime.h>
#include <cstdint>

// Problem-size upper bounds (actual sizes derived from in_sizes at launch).
#define NMAX 100000
#define EMAX 3200000
#define CAP  128     // bucket capacity per node (random E/N=32; overflow -> list)

// GEMM tiling
#define BLK   128   // threads per block (4 warps)
#define NPB   256   // nodes per block (64 per warp, 2 per thread)
#define KC    8     // K-chunk (floats per row per chunk)
#define NCH   64    // 512 / KC
#define NSTG  4     // cp.async pipeline stages (per-warp ring)

// Aggregation+MLP fusion
#define ABLK  512   // threads per agg block
#define ANPB  16    // nodes per agg block (one warp each)

// Scratch (allocation-free rule: __device__ globals; zero-initialized at load,
// and the pipeline re-zeroes its own counters each call => replay-safe).
__device__ int                  g_cnt[NMAX];       // in-degree (zeroed by k_pack)
__device__ int                  g_deg[NMAX];       // saved degree for k_agg
__device__ float                g_dinv[NMAX];      // rsqrt(cnt+1)
__device__ int                  g_bucket[(size_t)NMAX * CAP];
__device__ int                  g_ovf_cnt;         // live counter (reset by k_pack)
__device__ int                  g_ovf_cnt2;        // snapshot read by k_agg
__device__ int                  g_ovf_r[EMAX];
__device__ int                  g_ovf_c[EMAX];
__device__ __align__(16) float  g_y[NMAX * 16];    // xw[i], then scaled in-place

__device__ __forceinline__ int get_idx(const int* __restrict__ ei, long long p, int is64) {
    return is64 ? ei[p * 2] : ei[p];
}

// f32x2 packed-FMA helpers (Blackwell dual-FMA pipe; PTX-only).
__device__ __forceinline__ unsigned long long pk2(float v) {
    unsigned long long r;
    asm("mov.b64 %0, {%1, %1};" : "=l"(r) : "f"(v));
    return r;
}
__device__ __forceinline__ unsigned long long fma2(unsigned long long a,
                                                   unsigned long long b,
                                                   unsigned long long c) {
    unsigned long long d;
    asm("fma.rn.f32x2 %0, %1, %2, %3;" : "=l"(d) : "l"(a), "l"(b), "l"(c));
    return d;
}

// ---------------------------------------------------------------------------
// K1: bucket fill (with in-block dtype detect). bucket[c][pos] = r.
__global__ void k_fill(const int* __restrict__ ei, int E, int n) {
    __shared__ int s64;
    if (threadIdx.x == 0) {
        int is64 = 1;
        for (int k = 1; k < 64; k += 2)
            if (ei[k] != 0) { is64 = 0; break; }
        s64 = is64;
    }
    __syncthreads();
    int e = blockIdx.x * blockDim.x + threadIdx.x;
    if (e >= E) return;
    int is64 = s64;
    int r = get_idx(ei, (long long)e, is64);
    int c = get_idx(ei, (long long)E + e, is64);
    if ((unsigned)r >= (unsigned)n || (unsigned)c >= (unsigned)n) return;
    int pos = atomicAdd(&g_cnt[c], 1);
    if (pos < CAP) {
        g_bucket[(size_t)c * CAP + pos] = r;
    } else {
        int o = atomicAdd(&g_ovf_cnt, 1);
        if (o < EMAX) { g_ovf_r[o] = r; g_ovf_c[o] = c; }
    }
}

// ---------------------------------------------------------------------------
// K2: dinv + save degree + self-clean counters for the next graph replay.
__global__ void k_pack(int n) {
    int i = blockIdx.x * blockDim.x + threadIdx.x;
    if (i < n) {
        int cnt = g_cnt[i];
        g_deg[i]  = cnt;
        g_dinv[i] = rsqrtf((float)(cnt + 1));
        g_cnt[i] = 0;
    }
    if (i == 0) { g_ovf_cnt2 = g_ovf_cnt; g_ovf_cnt = 0; }
}

// ---------------------------------------------------------------------------
// K3: y = x @ Wg. Warp-owned 64-row slices; per-warp cp.async ring (4 stages);
// no block barriers in the mainloop (only one after the W smem load).
__device__ __forceinline__ void cp_async16(unsigned int sa, const void* ga) {
    asm volatile("cp.async.cg.shared.global [%0], [%1], 16;" :: "r"(sa), "l"(ga));
}

__device__ __forceinline__ void issue_chunk_w(unsigned int sxs, const float* __restrict__ x,
                                              int gr0, int n, int c, int slot, int lane) {
    unsigned int sbase = sxs + (unsigned int)slot * (NPB * KC * 4);
#pragma unroll
    for (int i = 0; i < 4; i++) {
        int idx = lane + i * 32;        // 0..127
        int row = idx >> 1;             // 0..63
        int q   = idx & 1;
        int gr  = gr0 + row;
        if (gr >= n) gr = n - 1;        // clamp (results discarded on write)
        const void* ga = x + (size_t)gr * 512 + c * KC + q * 4;
        unsigned int off = (unsigned int)(row * 32 + ((q ^ ((row >> 2) & 1)) << 4));
        cp_async16(sbase + off, ga);
    }
    asm volatile("cp.async.commit_group;" ::: "memory");
}

__global__ void __launch_bounds__(BLK, 3) k_gemm(const float* __restrict__ x,
                                                 const float* __restrict__ Wg, int n) {
    extern __shared__ float sm[];
    float* Ws = sm;             // 512*16 floats = 32KB
    float* xs = sm + 512 * 16;  // NSTG * 256 * 8 floats = 32KB

    int tid  = threadIdx.x;
    int lane = tid & 31;
    int warp = tid >> 5;
    int node0 = blockIdx.x * NPB;
    int gr0   = node0 + warp * 64;

    unsigned int sxs = (unsigned int)__cvta_generic_to_shared(xs)
                     + (unsigned int)warp * (64 * KC * 4);

#pragma unroll
    for (int p = 0; p < NSTG - 1; p++)
        issue_chunk_w(sxs, x, gr0, n, p, p, lane);

    for (int i = tid; i < (512 * 16) / 4; i += BLK)
        reinterpret_cast<float4*>(Ws)[i] = reinterpret_cast<const float4*>(Wg)[i];
    __syncthreads();  // the ONLY block barrier

    unsigned long long acc0[8], acc1[8];
#pragma unroll
    for (int j = 0; j < 8; j++) { acc0[j] = 0ull; acc1[j] = 0ull; }

    int s0 = (lane >> 2) & 1;
    const float* wslice = xs + warp * (64 * KC);

    for (int c = 0; c < NCH; c++) {
        asm volatile("cp.async.wait_group 2;" ::: "memory");
        if (c + NSTG - 1 < NCH)
            issue_chunk_w(sxs, x, gr0, n, c + NSTG - 1, (c + NSTG - 1) & (NSTG - 1), lane);
        else
            asm volatile("cp.async.commit_group;" ::: "memory");

        const float* bb = wslice + (c & (NSTG - 1)) * (NPB * KC);
#pragma unroll
        for (int q = 0; q < 2; q++) {
            float4 a  = *reinterpret_cast<const float4*>(bb + lane * 8 + ((q ^ s0) << 2));
            float4 b4 = *reinterpret_cast<const float4*>(bb + (lane + 32) * 8 + ((q ^ s0) << 2));
            const float* xa = &a.x;
            const float* xb = &b4.x;
#pragma unroll
            for (int d = 0; d < 4; d++) {
                int k = c * KC + q * 4 + d;
                const ulonglong2* wp = reinterpret_cast<const ulonglong2*>(Ws + k * 16);
                ulonglong2 wA = wp[0], wB = wp[1], wC = wp[2], wD = wp[3];
                unsigned long long xv0 = pk2(xa[d]);
                unsigned long long xv1 = pk2(xb[d]);
                acc0[0] = fma2(xv0, wA.x, acc0[0]);  acc1[0] = fma2(xv1, wA.x, acc1[0]);
                acc0[1] = fma2(xv0, wA.y, acc0[1]);  acc1[1] = fma2(xv1, wA.y, acc1[1]);
                acc0[2] = fma2(xv0, wB.x, acc0[2]);  acc1[2] = fma2(xv1, wB.x, acc1[2]);
                acc0[3] = fma2(xv0, wB.y, acc0[3]);  acc1[3] = fma2(xv1, wB.y, acc1[3]);
                acc0[4] = fma2(xv0, wC.x, acc0[4]);  acc1[4] = fma2(xv1, wC.x, acc1[4]);
                acc0[5] = fma2(xv0, wC.y, acc0[5]);  acc1[5] = fma2(xv1, wC.y, acc1[5]);
                acc0[6] = fma2(xv0, wD.x, acc0[6]);  acc1[6] = fma2(xv1, wD.x, acc1[6]);
                acc0[7] = fma2(xv0, wD.y, acc0[7]);  acc1[7] = fma2(xv1, wD.y, acc1[7]);
            }
        }
    }

    int i0 = gr0 + lane;
    int i1 = i0 + 32;
    if (i0 < n) {
        unsigned long long* yo = reinterpret_cast<unsigned long long*>(g_y + (size_t)i0 * 16);
#pragma unroll
        for (int j = 0; j < 8; j++) yo[j] = acc0[j];
    }
    if (i1 < n) {
        unsigned long long* yo = reinterpret_cast<unsigned long long*>(g_y + (size_t)i1 * 16);
#pragma unroll
        for (int j = 0; j < 8; j++) yo[j] = acc1[j];
    }
}

// ---------------------------------------------------------------------------
// K4: y'[i] = y[i] * dinv[i] (in-place). Two float4 per thread (ILP=2).
__global__ void k_scale(int n) {
    int i = (blockIdx.x * blockDim.x + threadIdx.x) * 2;   // over n*4 float4s
    if (i >= n * 4) return;
    float4* p0 = reinterpret_cast<float4*>(g_y) + i;
    float4 v0 = p0[0];
    float4 v1 = p0[1];
    float d0 = g_dinv[i >> 2];
    float d1 = g_dinv[(i + 1) >> 2];
    v0.x *= d0; v0.y *= d0; v0.z *= d0; v0.w *= d0;
    v1.x *= d1; v1.y *= d1; v1.z *= d1; v1.w *= d1;
    p0[0] = v0;
    p0[1] = v1;
}

// ---------------------------------------------------------------------------
// K5: fused gather-aggregate + MLP. 512 threads = 16 warps = 16 nodes/block.
// Each warp gathers its node (halves take alternating entries; lane&15 =
// feature; int4 bucket loads), writes relu(acc*dinv+bg) to smem; then
// threads 0-15 run the 3-layer MLP per node (per-thread, weights in smem).
__global__ void __launch_bounds__(ABLK) k_agg(
        const float* __restrict__ bg,
        const float* __restrict__ W1, const float* __restrict__ b1,
        const float* __restrict__ W2, const float* __restrict__ b2,
        const float* __restrict__ W3, const float* __restrict__ b3,
        float* __restrict__ out, int n) {
    __shared__ float sW1[256], sW2[512], sW3[32];
    __shared__ float sbg[16], sb1[16], sb2[32], sb3;
    __shared__ float sh0[ANPB][17];   // padded: threads 0-15 read conflict-free
    int t = threadIdx.x;
    if (t < 256) sW1[t] = W1[t];
    sW2[t] = W2[t];                   // ABLK == 512 covers it exactly
    if (t < 32) { sW3[t] = W3[t]; sb2[t] = b2[t]; }
    if (t < 16) { sb1[t] = b1[t]; sbg[t] = bg[t]; }
    if (t == 0) sb3 = b3[0];

    int warp = t >> 5;
    int lane = t & 31;
    int c    = blockIdx.x * ANPB + warp;
    int half = lane >> 4;
    unsigned int fb = (unsigned)(lane & 15);

    if (c < n) {
        float dc  = g_dinv[c];
        int   cnt = g_deg[c];
        int   m   = cnt < CAP ? cnt : CAP;
        const int4* bkv = reinterpret_cast<const int4*>(g_bucket + (size_t)c * CAP);

        float acc = (half == 0) ? g_y[((unsigned)c << 4) + fb] : 0.f;  // self loop

        int k4 = 0;
        for (; k4 * 4 + 7 < m; k4 += 2) {
            int4 a = __ldg(bkv + k4);
            int4 b = __ldg(bkv + k4 + 1);
            int r0 = half ? a.y : a.x;
            int r1 = half ? a.w : a.z;
            int r2 = half ? b.y : b.x;
            int r3 = half ? b.w : b.z;
            float v0 = __ldg(g_y + (((unsigned)r0) << 4) + fb);
            float v1 = __ldg(g_y + (((unsigned)r1) << 4) + fb);
            float v2 = __ldg(g_y + (((unsigned)r2) << 4) + fb);
            float v3 = __ldg(g_y + (((unsigned)r3) << 4) + fb);
            acc += v0 + v1 + v2 + v3;
        }
        const int* bk = reinterpret_cast<const int*>(bkv);
        for (int k = k4 * 4 + half; k < m; k += 2)
            acc += __ldg(g_y + (((unsigned)__ldg(bk + k)) << 4) + fb);

        if (cnt > CAP) {  // rare/adversarial: scan overflow snapshot
            int oc = g_ovf_cnt2; if (oc > EMAX) oc = EMAX;
            for (int i = half; i < oc; i += 2)
                if (g_ovf_c[i] == c)
                    acc += __ldg(g_y + (((unsigned)g_ovf_r[i]) << 4) + fb);
        }

        acc += __shfl_xor_sync(0xffffffff, acc, 16);
        if (lane < 16)
            sh0[warp][fb] = fmaxf(acc * dc + sbg[fb], 0.f);
    }
    __syncthreads();

    // MLP: threads 0-15 each finish one node.
    if (t < ANPB) {
        int i = blockIdx.x * ANPB + t;
        if (i < n) {
            float h0[16];
#pragma unroll
            for (int k = 0; k < 16; k++) h0[k] = sh0[t][k];

            float h1[16];
#pragma unroll
            for (int j = 0; j < 16; j++) {
                float s = sb1[j];
#pragma unroll
                for (int k = 0; k < 16; k++) s += h0[k] * sW1[k * 16 + j];
                h1[j] = fmaxf(s, 0.f);
            }

            float z = sb3;
#pragma unroll
            for (int j = 0; j < 32; j++) {
                float s = sb2[j];
#pragma unroll
                for (int k = 0; k < 16; k++) s += h1[k] * sW2[k * 32 + j];
                z += fmaxf(s, 0.f) * sW3[j];
            }

            out[i] = 1.f / (1.f + expf(-z));
        }
    }
}

// ---------------------------------------------------------------------------
extern "C" void kernel_launch(void* const* d_in, const int* in_sizes, int n_in,
                              void* d_out, int out_size) {
    const float* x  = (const float*)d_in[0];
    const int*   ei = (const int*)d_in[1];   // edge_index words (int32 or int64 LE)
    const float* Wg = (const float*)d_in[2];
    const float* bg = (const float*)d_in[3];
    const float* W1 = (const float*)d_in[4];
    const float* b1 = (const float*)d_in[5];
    const float* W2 = (const float*)d_in[6];
    const float* b2 = (const float*)d_in[7];
    const float* W3 = (const float*)d_in[8];
    const float* b3 = (const float*)d_in[9];
    float* out = (float*)d_out;

    int n = in_sizes[0] / 512;
    int E = in_sizes[1] / 2;   // element count, dtype-independent
    if (n > NMAX) n = NMAX;
    if (E > EMAX) E = EMAX;

    // One-time setup on the eager correctness call (NOT during capture).
    static int inited = 0;
    static cudaStream_t s2;
    static cudaEvent_t evFork, evGemm;
    int gemm_smem = (512 * 16 + NSTG * NPB * KC) * 4;  // 64KB
    if (!inited) {
        cudaFuncSetAttribute(k_gemm, cudaFuncAttributeMaxDynamicSharedMemorySize, gemm_smem);
        cudaStreamCreateWithFlags(&s2, cudaStreamNonBlocking);
        cudaEventCreateWithFlags(&evFork, cudaEventDisableTiming);
        cudaEventCreateWithFlags(&evGemm, cudaEventDisableTiming);
        inited = 1;
    }

    // Fork: gemm (x@Wg) is independent of the edge pipeline -> run on s2.
    cudaEventRecord(evFork, 0);
    cudaStreamWaitEvent(s2, evFork, 0);
    k_gemm<<<(n + NPB - 1) / NPB, BLK, gemm_smem, s2>>>(x, Wg, n);
    cudaEventRecord(evGemm, s2);

    // Edge pipeline on the capture (NULL) stream. Counters are zeroed either by
    // static zero-init (first call) or by the previous call's k_pack.
    k_fill<<<(E + 255) / 256, 256>>>(ei, E, n);
    k_pack<<<(n + 255) / 256, 256>>>(n);

    // Join, then scale y by dinv (needs both arms), fused gather+MLP.
    cudaStreamWaitEvent(0, evGemm, 0);
    k_scale<<<(n * 2 + 255) / 256, 256>>>(n);
    k_agg  <<<(n + ANPB - 1) / ANPB, ABLK>>>(bg, W1, b1, W2, b2, W3, b3, out, n);
}

// round 14
// speedup vs baseline: 1.7175x; 1.7175x over previous
#include <cuda_runtime.h>
#include <cstdint>

// Problem-size upper bounds (actual sizes derived from in_sizes at launch).
#define NMAX 100000
#define EMAX 3200000
#define CAP  128     // bucket capacity per node (random E/N=32; overflow -> list)

// GEMM tiling
#define BLK   128   // threads per block (4 warps)
#define NPB   256   // nodes per block (64 per warp, 2 per thread)
#define KC    8     // K-chunk (floats per row per chunk)
#define NCH   64    // 512 / KC
#define NSTG  4     // cp.async pipeline stages (per-warp ring)

// Scratch (allocation-free rule: __device__ globals; zero-initialized at load,
// and the pipeline re-zeroes its own counters each call => replay-safe).
__device__ int                  g_cnt[NMAX];       // in-degree (zeroed by k_pack)
__device__ int                  g_deg[NMAX];       // saved degree for k_agg
__device__ float                g_dinv[NMAX];      // rsqrt(cnt+1)
__device__ int                  g_bucket[(size_t)NMAX * CAP];
__device__ int                  g_ovf_cnt;         // live counter (reset by k_pack)
__device__ int                  g_ovf_cnt2;        // snapshot read by k_agg
__device__ int                  g_ovf_r[EMAX];
__device__ int                  g_ovf_c[EMAX];
__device__ __align__(16) float  g_y[NMAX * 16];    // xw[i], then scaled in-place
__device__ __align__(16) float  g_acc[NMAX * 16];  // (sum_in y'[r] + y'[c]) * dinv[c]

__device__ __forceinline__ int get_idx(const int* __restrict__ ei, long long p, int is64) {
    return is64 ? ei[p * 2] : ei[p];
}

// f32x2 packed-FMA helpers (Blackwell dual-FMA pipe; PTX-only).
__device__ __forceinline__ unsigned long long pk2(float v) {
    unsigned long long r;
    asm("mov.b64 %0, {%1, %1};" : "=l"(r) : "f"(v));
    return r;
}
__device__ __forceinline__ unsigned long long fma2(unsigned long long a,
                                                   unsigned long long b,
                                                   unsigned long long c) {
    unsigned long long d;
    asm("fma.rn.f32x2 %0, %1, %2, %3;" : "=l"(d) : "l"(a), "l"(b), "l"(c));
    return d;
}

// ---------------------------------------------------------------------------
// K1: bucket fill (with in-block dtype detect). bucket[c][pos] = r.
__global__ void k_fill(const int* __restrict__ ei, int E, int n) {
    __shared__ int s64;
    if (threadIdx.x == 0) {
        int is64 = 1;
        for (int k = 1; k < 64; k += 2)
            if (ei[k] != 0) { is64 = 0; break; }
        s64 = is64;
    }
    __syncthreads();
    int e = blockIdx.x * blockDim.x + threadIdx.x;
    if (e >= E) return;
    int is64 = s64;
    int r = get_idx(ei, (long long)e, is64);
    int c = get_idx(ei, (long long)E + e, is64);
    if ((unsigned)r >= (unsigned)n || (unsigned)c >= (unsigned)n) return;
    int pos = atomicAdd(&g_cnt[c], 1);
    if (pos < CAP) {
        g_bucket[(size_t)c * CAP + pos] = r;
    } else {
        int o = atomicAdd(&g_ovf_cnt, 1);
        if (o < EMAX) { g_ovf_r[o] = r; g_ovf_c[o] = c; }
    }
}

// ---------------------------------------------------------------------------
// K2: dinv + save degree + self-clean counters for the next graph replay.
__global__ void k_pack(int n) {
    int i = blockIdx.x * blockDim.x + threadIdx.x;
    if (i < n) {
        int cnt = g_cnt[i];
        g_deg[i]  = cnt;
        g_dinv[i] = rsqrtf((float)(cnt + 1));
        g_cnt[i] = 0;
    }
    if (i == 0) { g_ovf_cnt2 = g_ovf_cnt; g_ovf_cnt = 0; }
}

// ---------------------------------------------------------------------------
// K3: y = x @ Wg. Warp-owned 64-row slices; per-warp cp.async ring (4 stages);
// no block barriers in the mainloop (only one after the W smem load).
__device__ __forceinline__ void cp_async16(unsigned int sa, const void* ga) {
    asm volatile("cp.async.cg.shared.global [%0], [%1], 16;" :: "r"(sa), "l"(ga));
}

__device__ __forceinline__ void issue_chunk_w(unsigned int sxs, const float* __restrict__ x,
                                              int gr0, int n, int c, int slot, int lane) {
    unsigned int sbase = sxs + (unsigned int)slot * (NPB * KC * 4);
#pragma unroll
    for (int i = 0; i < 4; i++) {
        int idx = lane + i * 32;        // 0..127
        int row = idx >> 1;             // 0..63
        int q   = idx & 1;
        int gr  = gr0 + row;
        if (gr >= n) gr = n - 1;        // clamp (results discarded on write)
        const void* ga = x + (size_t)gr * 512 + c * KC + q * 4;
        unsigned int off = (unsigned int)(row * 32 + ((q ^ ((row >> 2) & 1)) << 4));
        cp_async16(sbase + off, ga);
    }
    asm volatile("cp.async.commit_group;" ::: "memory");
}

__global__ void __launch_bounds__(BLK, 3) k_gemm(const float* __restrict__ x,
                                                 const float* __restrict__ Wg, int n) {
    extern __shared__ float sm[];
    float* Ws = sm;             // 512*16 floats = 32KB
    float* xs = sm + 512 * 16;  // NSTG * 256 * 8 floats = 32KB

    int tid  = threadIdx.x;
    int lane = tid & 31;
    int warp = tid >> 5;
    int node0 = blockIdx.x * NPB;
    int gr0   = node0 + warp * 64;

    unsigned int sxs = (unsigned int)__cvta_generic_to_shared(xs)
                     + (unsigned int)warp * (64 * KC * 4);

#pragma unroll
    for (int p = 0; p < NSTG - 1; p++)
        issue_chunk_w(sxs, x, gr0, n, p, p, lane);

    for (int i = tid; i < (512 * 16) / 4; i += BLK)
        reinterpret_cast<float4*>(Ws)[i] = reinterpret_cast<const float4*>(Wg)[i];
    __syncthreads();  // the ONLY block barrier

    unsigned long long acc0[8], acc1[8];
#pragma unroll
    for (int j = 0; j < 8; j++) { acc0[j] = 0ull; acc1[j] = 0ull; }

    int s0 = (lane >> 2) & 1;
    const float* wslice = xs + warp * (64 * KC);

    for (int c = 0; c < NCH; c++) {
        asm volatile("cp.async.wait_group 2;" ::: "memory");
        if (c + NSTG - 1 < NCH)
            issue_chunk_w(sxs, x, gr0, n, c + NSTG - 1, (c + NSTG - 1) & (NSTG - 1), lane);
        else
            asm volatile("cp.async.commit_group;" ::: "memory");

        const float* bb = wslice + (c & (NSTG - 1)) * (NPB * KC);
#pragma unroll
        for (int q = 0; q < 2; q++) {
            float4 a  = *reinterpret_cast<const float4*>(bb + lane * 8 + ((q ^ s0) << 2));
            float4 b4 = *reinterpret_cast<const float4*>(bb + (lane + 32) * 8 + ((q ^ s0) << 2));
            const float* xa = &a.x;
            const float* xb = &b4.x;
#pragma unroll
            for (int d = 0; d < 4; d++) {
                int k = c * KC + q * 4 + d;
                const ulonglong2* wp = reinterpret_cast<const ulonglong2*>(Ws + k * 16);
                ulonglong2 wA = wp[0], wB = wp[1], wC = wp[2], wD = wp[3];
                unsigned long long xv0 = pk2(xa[d]);
                unsigned long long xv1 = pk2(xb[d]);
                acc0[0] = fma2(xv0, wA.x, acc0[0]);  acc1[0] = fma2(xv1, wA.x, acc1[0]);
                acc0[1] = fma2(xv0, wA.y, acc0[1]);  acc1[1] = fma2(xv1, wA.y, acc1[1]);
                acc0[2] = fma2(xv0, wB.x, acc0[2]);  acc1[2] = fma2(xv1, wB.x, acc1[2]);
                acc0[3] = fma2(xv0, wB.y, acc0[3]);  acc1[3] = fma2(xv1, wB.y, acc1[3]);
                acc0[4] = fma2(xv0, wC.x, acc0[4]);  acc1[4] = fma2(xv1, wC.x, acc1[4]);
                acc0[5] = fma2(xv0, wC.y, acc0[5]);  acc1[5] = fma2(xv1, wC.y, acc1[5]);
                acc0[6] = fma2(xv0, wD.x, acc0[6]);  acc1[6] = fma2(xv1, wD.x, acc1[6]);
                acc0[7] = fma2(xv0, wD.y, acc0[7]);  acc1[7] = fma2(xv1, wD.y, acc1[7]);
            }
        }
    }

    int i0 = gr0 + lane;
    int i1 = i0 + 32;
    if (i0 < n) {
        unsigned long long* yo = reinterpret_cast<unsigned long long*>(g_y + (size_t)i0 * 16);
#pragma unroll
        for (int j = 0; j < 8; j++) yo[j] = acc0[j];
    }
    if (i1 < n) {
        unsigned long long* yo = reinterpret_cast<unsigned long long*>(g_y + (size_t)i1 * 16);
#pragma unroll
        for (int j = 0; j < 8; j++) yo[j] = acc1[j];
    }
}

// ---------------------------------------------------------------------------
// K4: y'[i] = y[i] * dinv[i] (in-place). One float4 per thread.
__global__ void k_scale(int n) {
    int i = blockIdx.x * blockDim.x + threadIdx.x;   // over n*4 float4s
    if (i >= n * 4) return;
    float d = g_dinv[i >> 2];
    float4* p = reinterpret_cast<float4*>(g_y) + i;
    float4 v = *p;
    v.x *= d; v.y *= d; v.z *= d; v.w *= d;
    *p = v;
}

// ---------------------------------------------------------------------------
// K5: gather-aggregate over pre-scaled y'. One warp per node; halves take
// alternating bucket entries (int4 index loads); lane&15 = feature.
// Seed = y'[c] (self loop). Writes g_acc = (sum) * dinv[c].
__global__ void k_agg(int n) {
    int warp = (blockIdx.x * blockDim.x + threadIdx.x) >> 5;
    int lane = threadIdx.x & 31;
    if (warp >= n) return;
    int c    = warp;
    int half = lane >> 4;
    unsigned int fb = (unsigned)(lane & 15);

    float dc  = g_dinv[c];
    int   cnt = g_deg[c];
    int   m   = cnt < CAP ? cnt : CAP;
    const int4* bkv = reinterpret_cast<const int4*>(g_bucket + (size_t)c * CAP);

    float acc = (half == 0) ? g_y[((unsigned)c << 4) + fb] : 0.f;  // self loop

    int k4 = 0;
    for (; k4 * 4 + 7 < m; k4 += 2) {
        int4 a = __ldg(bkv + k4);
        int4 b = __ldg(bkv + k4 + 1);
        int r0 = half ? a.y : a.x;
        int r1 = half ? a.w : a.z;
        int r2 = half ? b.y : b.x;
        int r3 = half ? b.w : b.z;
        float v0 = __ldg(g_y + (((unsigned)r0) << 4) + fb);
        float v1 = __ldg(g_y + (((unsigned)r1) << 4) + fb);
        float v2 = __ldg(g_y + (((unsigned)r2) << 4) + fb);
        float v3 = __ldg(g_y + (((unsigned)r3) << 4) + fb);
        acc += v0 + v1 + v2 + v3;
    }
    const int* bk = reinterpret_cast<const int*>(bkv);
    for (int k = k4 * 4 + half; k < m; k += 2)
        acc += __ldg(g_y + (((unsigned)__ldg(bk + k)) << 4) + fb);

    if (cnt > CAP) {  // rare/adversarial: scan overflow snapshot for this node
        int oc = g_ovf_cnt2; if (oc > EMAX) oc = EMAX;
        for (int i = half; i < oc; i += 2)
            if (g_ovf_c[i] == c)
                acc += __ldg(g_y + (((unsigned)g_ovf_r[i]) << 4) + fb);
    }

    acc += __shfl_xor_sync(0xffffffff, acc, 16);
    if (lane < 16) g_acc[((unsigned)c << 4) + fb] = acc * dc;
}

// ---------------------------------------------------------------------------
// K6: finalize: h0 = relu(acc + bg); 3-layer MLP + sigmoid. One node/thread.
__global__ void k_final(const float* __restrict__ bg,
                        const float* __restrict__ W1, const float* __restrict__ b1,
                        const float* __restrict__ W2, const float* __restrict__ b2,
                        const float* __restrict__ W3, const float* __restrict__ b3,
                        float* __restrict__ out, int n) {
    __shared__ float sW1[256], sW2[512], sW3[32];
    __shared__ float sbg[16], sb1[16], sb2[32], sb3;
    int t = threadIdx.x;
    if (t < 256) sW1[t] = W1[t];
    for (int q = t; q < 512; q += blockDim.x) sW2[q] = W2[q];
    if (t < 32) { sW3[t] = W3[t]; sb2[t] = b2[t]; }
    if (t < 16) { sb1[t] = b1[t]; sbg[t] = bg[t]; }
    if (t == 0) sb3 = b3[0];
    __syncthreads();

    int i = blockIdx.x * blockDim.x + t;
    if (i >= n) return;

    const float4* ar = reinterpret_cast<const float4*>(g_acc) + (size_t)i * 4;

    float h0[16];
#pragma unroll
    for (int q = 0; q < 4; q++) {
        float4 a = ar[q];
        h0[q * 4 + 0] = fmaxf(a.x + sbg[q * 4 + 0], 0.f);
        h0[q * 4 + 1] = fmaxf(a.y + sbg[q * 4 + 1], 0.f);
        h0[q * 4 + 2] = fmaxf(a.z + sbg[q * 4 + 2], 0.f);
        h0[q * 4 + 3] = fmaxf(a.w + sbg[q * 4 + 3], 0.f);
    }

    float h1[16];
#pragma unroll
    for (int j = 0; j < 16; j++) {
        float s = sb1[j];
#pragma unroll
        for (int k = 0; k < 16; k++) s += h0[k] * sW1[k * 16 + j];
        h1[j] = fmaxf(s, 0.f);
    }

    float z = sb3;
#pragma unroll
    for (int j = 0; j < 32; j++) {
        float s = sb2[j];
#pragma unroll
        for (int k = 0; k < 16; k++) s += h1[k] * sW2[k * 32 + j];
        z += fmaxf(s, 0.f) * sW3[j];
    }

    out[i] = 1.f / (1.f + expf(-z));
}

// ---------------------------------------------------------------------------
extern "C" void kernel_launch(void* const* d_in, const int* in_sizes, int n_in,
                              void* d_out, int out_size) {
    const float* x  = (const float*)d_in[0];
    const int*   ei = (const int*)d_in[1];   // edge_index words (int32 or int64 LE)
    const float* Wg = (const float*)d_in[2];
    const float* bg = (const float*)d_in[3];
    const float* W1 = (const float*)d_in[4];
    const float* b1 = (const float*)d_in[5];
    const float* W2 = (const float*)d_in[6];
    const float* b2 = (const float*)d_in[7];
    const float* W3 = (const float*)d_in[8];
    const float* b3 = (const float*)d_in[9];
    float* out = (float*)d_out;

    int n = in_sizes[0] / 512;
    int E = in_sizes[1] / 2;   // element count, dtype-independent
    if (n > NMAX) n = NMAX;
    if (E > EMAX) E = EMAX;

    // One-time setup on the eager correctness call (NOT during capture).
    static int inited = 0;
    static cudaStream_t s2;
    static cudaEvent_t evFork, evGemm;
    int gemm_smem = (512 * 16 + NSTG * NPB * KC) * 4;  // 64KB
    if (!inited) {
        cudaFuncSetAttribute(k_gemm, cudaFuncAttributeMaxDynamicSharedMemorySize, gemm_smem);
        cudaStreamCreateWithFlags(&s2, cudaStreamNonBlocking);
        cudaEventCreateWithFlags(&evFork, cudaEventDisableTiming);
        cudaEventCreateWithFlags(&evGemm, cudaEventDisableTiming);
        inited = 1;
    }

    // Fork: gemm (x@Wg) is independent of the edge pipeline -> run on s2.
    cudaEventRecord(evFork, 0);
    cudaStreamWaitEvent(s2, evFork, 0);
    k_gemm<<<(n + NPB - 1) / NPB, BLK, gemm_smem, s2>>>(x, Wg, n);
    cudaEventRecord(evGemm, s2);

    // Edge pipeline on the capture (NULL) stream. Counters are zeroed either by
    // static zero-init (first call) or by the previous call's k_pack.
    k_fill<<<(E + 255) / 256, 256>>>(ei, E, n);
    k_pack<<<(n + 255) / 256, 256>>>(n);

    // Join, then scale y by dinv (needs both arms), gather, MLP.
    cudaStreamWaitEvent(0, evGemm, 0);
    k_scale<<<(n * 4 + 255) / 256, 256>>>(n);
    k_agg  <<<(n * 32 + 255) / 256, 256>>>(n);
    k_final<<<(n + 255) / 256, 256>>>(bg, W1, b1, W2, b2, W3, b3, out, n);
}

// round 16
// speedup vs baseline: 1.8508x; 1.0776x over previous
#include <cuda_runtime.h>
#include <cstdint>

// Problem-size upper bounds (actual sizes derived from in_sizes at launch).
#define NMAX 100000
#define EMAX 3200000
#define CAP  128     // bucket capacity per node (random E/N=32; overflow -> list)

// GEMM tiling
#define BLK   128   // threads per block (4 warps)
#define NPB   256   // nodes per block (64 per warp, 2 per thread)
#define KC    8     // K-chunk (floats per row per chunk)
#define NCH   64    // 512 / KC
#define NSTG  4     // cp.async pipeline stages (per-warp ring)

// Scratch (allocation-free rule: __device__ globals; zero-initialized at load,
// and the pipeline re-zeroes its own counters each call => replay-safe).
__device__ int                  g_cnt[NMAX];       // in-degree (zeroed by k_agg)
__device__ int                  g_bucket[(size_t)NMAX * CAP];
__device__ int                  g_ovf_cnt;         // live counter (reset by k_scale)
__device__ int                  g_ovf_cnt2;        // snapshot read by k_agg
__device__ int                  g_ovf_r[EMAX];
__device__ int                  g_ovf_c[EMAX];
__device__ __align__(16) float  g_y[NMAX * 16];    // xw[i], then scaled in-place
__device__ __align__(16) float  g_acc[NMAX * 16];  // (sum_in y'[r] + y'[c]) * dinv[c]

__device__ __forceinline__ int get_idx(const int* __restrict__ ei, long long p, int is64) {
    return is64 ? ei[p * 2] : ei[p];
}

// f32x2 packed-FMA helpers (Blackwell dual-FMA pipe; PTX-only).
__device__ __forceinline__ unsigned long long pk2(float v) {
    unsigned long long r;
    asm("mov.b64 %0, {%1, %1};" : "=l"(r) : "f"(v));
    return r;
}
__device__ __forceinline__ unsigned long long fma2(unsigned long long a,
                                                   unsigned long long b,
                                                   unsigned long long c) {
    unsigned long long d;
    asm("fma.rn.f32x2 %0, %1, %2, %3;" : "=l"(d) : "l"(a), "l"(b), "l"(c));
    return d;
}

// ---------------------------------------------------------------------------
// K1: bucket fill (with in-block dtype detect). bucket[c][pos] = r.
__global__ void k_fill(const int* __restrict__ ei, int E, int n) {
    __shared__ int s64;
    if (threadIdx.x == 0) {
        int is64 = 1;
        for (int k = 1; k < 64; k += 2)
            if (ei[k] != 0) { is64 = 0; break; }
        s64 = is64;
    }
    __syncthreads();
    int e = blockIdx.x * blockDim.x + threadIdx.x;
    if (e >= E) return;
    int is64 = s64;
    int r = get_idx(ei, (long long)e, is64);
    int c = get_idx(ei, (long long)E + e, is64);
    if ((unsigned)r >= (unsigned)n || (unsigned)c >= (unsigned)n) return;
    int pos = atomicAdd(&g_cnt[c], 1);
    if (pos < CAP) {
        g_bucket[(size_t)c * CAP + pos] = r;
    } else {
        int o = atomicAdd(&g_ovf_cnt, 1);
        if (o < EMAX) { g_ovf_r[o] = r; g_ovf_c[o] = c; }
    }
}

// ---------------------------------------------------------------------------
// K2: y = x @ Wg. Warp-owned 64-row slices; per-warp cp.async ring (4 stages);
// no block barriers in the mainloop (only one after the W smem load).
__device__ __forceinline__ void cp_async16(unsigned int sa, const void* ga) {
    asm volatile("cp.async.cg.shared.global [%0], [%1], 16;" :: "r"(sa), "l"(ga));
}

__device__ __forceinline__ void issue_chunk_w(unsigned int sxs, const float* __restrict__ x,
                                              int gr0, int n, int c, int slot, int lane) {
    unsigned int sbase = sxs + (unsigned int)slot * (NPB * KC * 4);
#pragma unroll
    for (int i = 0; i < 4; i++) {
        int idx = lane + i * 32;        // 0..127
        int row = idx >> 1;             // 0..63
        int q   = idx & 1;
        int gr  = gr0 + row;
        if (gr >= n) gr = n - 1;        // clamp (results discarded on write)
        const void* ga = x + (size_t)gr * 512 + c * KC + q * 4;
        unsigned int off = (unsigned int)(row * 32 + ((q ^ ((row >> 2) & 1)) << 4));
        cp_async16(sbase + off, ga);
    }
    asm volatile("cp.async.commit_group;" ::: "memory");
}

__global__ void __launch_bounds__(BLK, 3) k_gemm(const float* __restrict__ x,
                                                 const float* __restrict__ Wg, int n) {
    extern __shared__ float sm[];
    float* Ws = sm;             // 512*16 floats = 32KB
    float* xs = sm + 512 * 16;  // NSTG * 256 * 8 floats = 32KB

    int tid  = threadIdx.x;
    int lane = tid & 31;
    int warp = tid >> 5;
    int node0 = blockIdx.x * NPB;
    int gr0   = node0 + warp * 64;

    unsigned int sxs = (unsigned int)__cvta_generic_to_shared(xs)
                     + (unsigned int)warp * (64 * KC * 4);

#pragma unroll
    for (int p = 0; p < NSTG - 1; p++)
        issue_chunk_w(sxs, x, gr0, n, p, p, lane);

    for (int i = tid; i < (512 * 16) / 4; i += BLK)
        reinterpret_cast<float4*>(Ws)[i] = reinterpret_cast<const float4*>(Wg)[i];
    __syncthreads();  // the ONLY block barrier

    unsigned long long acc0[8], acc1[8];
#pragma unroll
    for (int j = 0; j < 8; j++) { acc0[j] = 0ull; acc1[j] = 0ull; }

    int s0 = (lane >> 2) & 1;
    const float* wslice = xs + warp * (64 * KC);

    for (int c = 0; c < NCH; c++) {
        asm volatile("cp.async.wait_group 2;" ::: "memory");
        if (c + NSTG - 1 < NCH)
            issue_chunk_w(sxs, x, gr0, n, c + NSTG - 1, (c + NSTG - 1) & (NSTG - 1), lane);
        else
            asm volatile("cp.async.commit_group;" ::: "memory");

        const float* bb = wslice + (c & (NSTG - 1)) * (NPB * KC);
#pragma unroll
        for (int q = 0; q < 2; q++) {
            float4 a  = *reinterpret_cast<const float4*>(bb + lane * 8 + ((q ^ s0) << 2));
            float4 b4 = *reinterpret_cast<const float4*>(bb + (lane + 32) * 8 + ((q ^ s0) << 2));
            const float* xa = &a.x;
            const float* xb = &b4.x;
#pragma unroll
            for (int d = 0; d < 4; d++) {
                int k = c * KC + q * 4 + d;
                const ulonglong2* wp = reinterpret_cast<const ulonglong2*>(Ws + k * 16);
                ulonglong2 wA = wp[0], wB = wp[1], wC = wp[2], wD = wp[3];
                unsigned long long xv0 = pk2(xa[d]);
                unsigned long long xv1 = pk2(xb[d]);
                acc0[0] = fma2(xv0, wA.x, acc0[0]);  acc1[0] = fma2(xv1, wA.x, acc1[0]);
                acc0[1] = fma2(xv0, wA.y, acc0[1]);  acc1[1] = fma2(xv1, wA.y, acc1[1]);
                acc0[2] = fma2(xv0, wB.x, acc0[2]);  acc1[2] = fma2(xv1, wB.x, acc1[2]);
                acc0[3] = fma2(xv0, wB.y, acc0[3]);  acc1[3] = fma2(xv1, wB.y, acc1[3]);
                acc0[4] = fma2(xv0, wC.x, acc0[4]);  acc1[4] = fma2(xv1, wC.x, acc1[4]);
                acc0[5] = fma2(xv0, wC.y, acc0[5]);  acc1[5] = fma2(xv1, wC.y, acc1[5]);
                acc0[6] = fma2(xv0, wD.x, acc0[6]);  acc1[6] = fma2(xv1, wD.x, acc1[6]);
                acc0[7] = fma2(xv0, wD.y, acc0[7]);  acc1[7] = fma2(xv1, wD.y, acc1[7]);
            }
        }
    }

    int i0 = gr0 + lane;
    int i1 = i0 + 32;
    if (i0 < n) {
        unsigned long long* yo = reinterpret_cast<unsigned long long*>(g_y + (size_t)i0 * 16);
#pragma unroll
        for (int j = 0; j < 8; j++) yo[j] = acc0[j];
    }
    if (i1 < n) {
        unsigned long long* yo = reinterpret_cast<unsigned long long*>(g_y + (size_t)i1 * 16);
#pragma unroll
        for (int j = 0; j < 8; j++) yo[j] = acc1[j];
    }
}

// ---------------------------------------------------------------------------
// K3: y'[i] = y[i] * rsqrt(cnt[i]+1) (in-place). One float4 per thread.
// Thread 0 snapshots + resets the overflow counter for this call.
__global__ void k_scale(int n) {
    int i = blockIdx.x * blockDim.x + threadIdx.x;   // over n*4 float4s
    if (blockIdx.x == 0 && threadIdx.x == 0) {
        g_ovf_cnt2 = g_ovf_cnt;
        g_ovf_cnt = 0;
    }
    if (i >= n * 4) return;
    float d = rsqrtf((float)(g_cnt[i >> 2] + 1));
    float4* p = reinterpret_cast<float4*>(g_y) + i;
    float4 v = *p;
    v.x *= d; v.y *= d; v.z *= d; v.w *= d;
    *p = v;
}

// ---------------------------------------------------------------------------
// K4: gather-aggregate over pre-scaled y'. One warp per node. Lane layout:
// sub = lane>>2 (entry slot 0..7), q = lane&3 (feature quad). One warp
// instruction gathers 8 entries x 16B = 512B. 2-way unrolled (16 entries/it).
// Reduce across sub via shfl-xor {4,8,16}; lanes 0-3 add self loop, scale by
// dinv, store float4. Lane 0 zeroes g_cnt[c] for the next replay.
__global__ void k_agg(int n) {
    int warp = (blockIdx.x * blockDim.x + threadIdx.x) >> 5;
    int lane = threadIdx.x & 31;
    if (warp >= n) return;
    int c   = warp;
    int sub = lane >> 2;
    int q   = lane & 3;

    int cnt = g_cnt[c];
    int m   = cnt < CAP ? cnt : CAP;
    const int* bk = g_bucket + (size_t)c * CAP;

    float4 accA = make_float4(0.f, 0.f, 0.f, 0.f);
    float4 accB = make_float4(0.f, 0.f, 0.f, 0.f);

    int k8 = 0;
    for (; k8 + 16 <= m; k8 += 16) {
        int rA = __ldg(bk + k8 + sub);
        int rB = __ldg(bk + k8 + 8 + sub);
        float4 vA = *reinterpret_cast<const float4*>(g_y + (((unsigned)rA) << 4) + (q << 2));
        float4 vB = *reinterpret_cast<const float4*>(g_y + (((unsigned)rB) << 4) + (q << 2));
        accA.x += vA.x; accA.y += vA.y; accA.z += vA.z; accA.w += vA.w;
        accB.x += vB.x; accB.y += vB.y; accB.z += vB.z; accB.w += vB.w;
    }
    for (; k8 < m; k8 += 8) {                 // <=2 masked tail chunks
        int e = k8 + sub;
        if (e < m) {
            int r = __ldg(bk + e);
            float4 v = *reinterpret_cast<const float4*>(g_y + (((unsigned)r) << 4) + (q << 2));
            accA.x += v.x; accA.y += v.y; accA.z += v.z; accA.w += v.w;
        }
    }
    accA.x += accB.x; accA.y += accB.y; accA.z += accB.z; accA.w += accB.w;

    if (cnt > CAP && lane < 4) {  // rare/adversarial: scan overflow snapshot
        int oc = g_ovf_cnt2; if (oc > EMAX) oc = EMAX;
        for (int i = 0; i < oc; i++)
            if (g_ovf_c[i] == c) {
                float4 v = *reinterpret_cast<const float4*>(
                    g_y + (((unsigned)g_ovf_r[i]) << 4) + (lane << 2));
                accA.x += v.x; accA.y += v.y; accA.z += v.z; accA.w += v.w;
            }
    }

#pragma unroll
    for (int off = 4; off <= 16; off <<= 1) {
        accA.x += __shfl_xor_sync(0xffffffff, accA.x, off);
        accA.y += __shfl_xor_sync(0xffffffff, accA.y, off);
        accA.z += __shfl_xor_sync(0xffffffff, accA.z, off);
        accA.w += __shfl_xor_sync(0xffffffff, accA.w, off);
    }

    if (lane < 4) {
        float dc = rsqrtf((float)(cnt + 1));
        float4 self = *reinterpret_cast<const float4*>(g_y + (((unsigned)c) << 4) + (lane << 2));
        float4 o;
        o.x = (accA.x + self.x) * dc;
        o.y = (accA.y + self.y) * dc;
        o.z = (accA.z + self.z) * dc;
        o.w = (accA.w + self.w) * dc;
        *reinterpret_cast<float4*>(g_acc + (((unsigned)c) << 4) + (lane << 2)) = o;
    }
    if (lane == 0) g_cnt[c] = 0;   // self-clean for next replay
}

// ---------------------------------------------------------------------------
// K5: finalize: h0 = relu(acc + bg); 3-layer MLP + sigmoid. One node/thread.
__global__ void k_final(const float* __restrict__ bg,
                        const float* __restrict__ W1, const float* __restrict__ b1,
                        const float* __restrict__ W2, const float* __restrict__ b2,
                        const float* __restrict__ W3, const float* __restrict__ b3,
                        float* __restrict__ out, int n) {
    __shared__ float sW1[256], sW2[512], sW3[32];
    __shared__ float sbg[16], sb1[16], sb2[32], sb3;
    int t = threadIdx.x;
    if (t < 256) sW1[t] = W1[t];
    for (int q = t; q < 512; q += blockDim.x) sW2[q] = W2[q];
    if (t < 32) { sW3[t] = W3[t]; sb2[t] = b2[t]; }
    if (t < 16) { sb1[t] = b1[t]; sbg[t] = bg[t]; }
    if (t == 0) sb3 = b3[0];
    __syncthreads();

    int i = blockIdx.x * blockDim.x + t;
    if (i >= n) return;

    const float4* ar = reinterpret_cast<const float4*>(g_acc) + (size_t)i * 4;

    float h0[16];
#pragma unroll
    for (int q = 0; q < 4; q++) {
        float4 a = ar[q];
        h0[q * 4 + 0] = fmaxf(a.x + sbg[q * 4 + 0], 0.f);
        h0[q * 4 + 1] = fmaxf(a.y + sbg[q * 4 + 1], 0.f);
        h0[q * 4 + 2] = fmaxf(a.z + sbg[q * 4 + 2], 0.f);
        h0[q * 4 + 3] = fmaxf(a.w + sbg[q * 4 + 3], 0.f);
    }

    float h1[16];
#pragma unroll
    for (int j = 0; j < 16; j++) {
        float s = sb1[j];
#pragma unroll
        for (int k = 0; k < 16; k++) s += h0[k] * sW1[k * 16 + j];
        h1[j] = fmaxf(s, 0.f);
    }

    float z = sb3;
#pragma unroll
    for (int j = 0; j < 32; j++) {
        float s = sb2[j];
#pragma unroll
        for (int k = 0; k < 16; k++) s += h1[k] * sW2[k * 32 + j];
        z += fmaxf(s, 0.f) * sW3[j];
    }

    out[i] = 1.f / (1.f + expf(-z));
}

// ---------------------------------------------------------------------------
extern "C" void kernel_launch(void* const* d_in, const int* in_sizes, int n_in,
                              void* d_out, int out_size) {
    const float* x  = (const float*)d_in[0];
    const int*   ei = (const int*)d_in[1];   // edge_index words (int32 or int64 LE)
    const float* Wg = (const float*)d_in[2];
    const float* bg = (const float*)d_in[3];
    const float* W1 = (const float*)d_in[4];
    const float* b1 = (const float*)d_in[5];
    const float* W2 = (const float*)d_in[6];
    const float* b2 = (const float*)d_in[7];
    const float* W3 = (const float*)d_in[8];
    const float* b3 = (const float*)d_in[9];
    float* out = (float*)d_out;

    int n = in_sizes[0] / 512;
    int E = in_sizes[1] / 2;   // element count, dtype-independent
    if (n > NMAX) n = NMAX;
    if (E > EMAX) E = EMAX;

    // One-time setup on the eager correctness call (NOT during capture).
    static int inited = 0;
    static cudaStream_t s2;
    static cudaEvent_t evFork, evGemm;
    int gemm_smem = (512 * 16 + NSTG * NPB * KC) * 4;  // 64KB
    if (!inited) {
        cudaFuncSetAttribute(k_gemm, cudaFuncAttributeMaxDynamicSharedMemorySize, gemm_smem);
        cudaStreamCreateWithFlags(&s2, cudaStreamNonBlocking);
        cudaEventCreateWithFlags(&evFork, cudaEventDisableTiming);
        cudaEventCreateWithFlags(&evGemm, cudaEventDisableTiming);
        inited = 1;
    }

    // Fork: gemm (x@Wg) is independent of the edge pipeline -> run on s2.
    cudaEventRecord(evFork, 0);
    cudaStreamWaitEvent(s2, evFork, 0);
    k_gemm<<<(n + NPB - 1) / NPB, BLK, gemm_smem, s2>>>(x, Wg, n);
    cudaEventRecord(evGemm, s2);

    // Edge arm on the capture (NULL) stream: just the bucket fill now.
    k_fill<<<(E + 255) / 256, 256>>>(ei, E, n);

    // Join, then scale y by dinv (needs both arms), gather, MLP.
    cudaStreamWaitEvent(0, evGemm, 0);
    k_scale<<<(n * 4 + 255) / 256, 256>>>(n);
    k_agg  <<<(n * 32 + 255) / 256, 256>>>(n);
    k_final<<<(n + 255) / 256, 256>>>(bg, W1, b1, W2, b2, W3, b3, out, n);
}

// round 17
// speedup vs baseline: 1.8713x; 1.0111x over previous
#include <cuda_runtime.h>
#include <cstdint>

// Problem-size upper bounds (actual sizes derived from in_sizes at launch).
#define NMAX 100000
#define EMAX 3200000
#define CAP  128     // bucket capacity per node (random E/N=32; overflow -> list)

// GEMM tiling
#define BLK   128   // threads per block (4 warps)
#define NPB   256   // nodes per block (64 per warp, 2 per thread)
#define KC    8     // K-chunk (floats per row per chunk)
#define NCH   64    // 512 / KC
#define NSTG  4     // cp.async pipeline stages (per-warp ring)

// Scratch (allocation-free rule: __device__ globals; zero-initialized at load,
// and the pipeline re-zeroes its own counters each call => replay-safe).
__device__ int                  g_cnt[NMAX];       // in-degree (zeroed by k_agg)
__device__ int                  g_bucket[(size_t)NMAX * CAP];
__device__ int                  g_ovf_cnt;         // live counter (reset by k_scale)
__device__ int                  g_ovf_cnt2;        // snapshot read by k_agg
__device__ int                  g_ovf_r[EMAX];
__device__ int                  g_ovf_c[EMAX];
__device__ __align__(16) float  g_y[NMAX * 16];    // xw[i], then scaled in-place
__device__ __align__(16) float  g_acc[NMAX * 16];  // (sum_in y'[r] + y'[c]) * dinv[c]

__device__ __forceinline__ int get_idx(const int* __restrict__ ei, long long p, int is64) {
    return is64 ? ei[p * 2] : ei[p];
}

// f32x2 packed-FMA helpers (Blackwell dual-FMA pipe; PTX-only).
__device__ __forceinline__ unsigned long long pk2(float v) {
    unsigned long long r;
    asm("mov.b64 %0, {%1, %1};" : "=l"(r) : "f"(v));
    return r;
}
__device__ __forceinline__ unsigned long long fma2(unsigned long long a,
                                                   unsigned long long b,
                                                   unsigned long long c) {
    unsigned long long d;
    asm("fma.rn.f32x2 %0, %1, %2, %3;" : "=l"(d) : "l"(a), "l"(b), "l"(c));
    return d;
}

// ---------------------------------------------------------------------------
// K1: bucket fill (with in-block dtype detect). bucket[c][pos] = r.
__global__ void k_fill(const int* __restrict__ ei, int E, int n) {
    __shared__ int s64;
    if (threadIdx.x == 0) {
        int is64 = 1;
        for (int k = 1; k < 64; k += 2)
            if (ei[k] != 0) { is64 = 0; break; }
        s64 = is64;
    }
    __syncthreads();
    int e = blockIdx.x * blockDim.x + threadIdx.x;
    if (e >= E) return;
    int is64 = s64;
    int r = get_idx(ei, (long long)e, is64);
    int c = get_idx(ei, (long long)E + e, is64);
    if ((unsigned)r >= (unsigned)n || (unsigned)c >= (unsigned)n) return;
    int pos = atomicAdd(&g_cnt[c], 1);
    if (pos < CAP) {
        g_bucket[(size_t)c * CAP + pos] = r;
    } else {
        int o = atomicAdd(&g_ovf_cnt, 1);
        if (o < EMAX) { g_ovf_r[o] = r; g_ovf_c[o] = c; }
    }
}

// ---------------------------------------------------------------------------
// K2: y = x @ Wg. Warp-owned 64-row slices; per-warp cp.async ring (4 stages);
// no block barriers in the mainloop (only one after the W smem load).
__device__ __forceinline__ void cp_async16(unsigned int sa, const void* ga) {
    asm volatile("cp.async.cg.shared.global [%0], [%1], 16;" :: "r"(sa), "l"(ga));
}

__device__ __forceinline__ void issue_chunk_w(unsigned int sxs, const float* __restrict__ x,
                                              int gr0, int n, int c, int slot, int lane) {
    unsigned int sbase = sxs + (unsigned int)slot * (NPB * KC * 4);
#pragma unroll
    for (int i = 0; i < 4; i++) {
        int idx = lane + i * 32;        // 0..127
        int row = idx >> 1;             // 0..63
        int q   = idx & 1;
        int gr  = gr0 + row;
        if (gr >= n) gr = n - 1;        // clamp (results discarded on write)
        const void* ga = x + (size_t)gr * 512 + c * KC + q * 4;
        unsigned int off = (unsigned int)(row * 32 + ((q ^ ((row >> 2) & 1)) << 4));
        cp_async16(sbase + off, ga);
    }
    asm volatile("cp.async.commit_group;" ::: "memory");
}

__global__ void __launch_bounds__(BLK, 3) k_gemm(const float* __restrict__ x,
                                                 const float* __restrict__ Wg, int n) {
    extern __shared__ float sm[];
    float* Ws = sm;             // 512*16 floats = 32KB
    float* xs = sm + 512 * 16;  // NSTG * 256 * 8 floats = 32KB

    int tid  = threadIdx.x;
    int lane = tid & 31;
    int warp = tid >> 5;
    int node0 = blockIdx.x * NPB;
    int gr0   = node0 + warp * 64;

    unsigned int sxs = (unsigned int)__cvta_generic_to_shared(xs)
                     + (unsigned int)warp * (64 * KC * 4);

#pragma unroll
    for (int p = 0; p < NSTG - 1; p++)
        issue_chunk_w(sxs, x, gr0, n, p, p, lane);

    for (int i = tid; i < (512 * 16) / 4; i += BLK)
        reinterpret_cast<float4*>(Ws)[i] = reinterpret_cast<const float4*>(Wg)[i];
    __syncthreads();  // the ONLY block barrier

    unsigned long long acc0[8], acc1[8];
#pragma unroll
    for (int j = 0; j < 8; j++) { acc0[j] = 0ull; acc1[j] = 0ull; }

    int s0 = (lane >> 2) & 1;
    const float* wslice = xs + warp * (64 * KC);

    for (int c = 0; c < NCH; c++) {
        asm volatile("cp.async.wait_group 2;" ::: "memory");
        if (c + NSTG - 1 < NCH)
            issue_chunk_w(sxs, x, gr0, n, c + NSTG - 1, (c + NSTG - 1) & (NSTG - 1), lane);
        else
            asm volatile("cp.async.commit_group;" ::: "memory");

        const float* bb = wslice + (c & (NSTG - 1)) * (NPB * KC);
#pragma unroll
        for (int q = 0; q < 2; q++) {
            float4 a  = *reinterpret_cast<const float4*>(bb + lane * 8 + ((q ^ s0) << 2));
            float4 b4 = *reinterpret_cast<const float4*>(bb + (lane + 32) * 8 + ((q ^ s0) << 2));
            const float* xa = &a.x;
            const float* xb = &b4.x;
#pragma unroll
            for (int d = 0; d < 4; d++) {
                int k = c * KC + q * 4 + d;
                const ulonglong2* wp = reinterpret_cast<const ulonglong2*>(Ws + k * 16);
                ulonglong2 wA = wp[0], wB = wp[1], wC = wp[2], wD = wp[3];
                unsigned long long xv0 = pk2(xa[d]);
                unsigned long long xv1 = pk2(xb[d]);
                acc0[0] = fma2(xv0, wA.x, acc0[0]);  acc1[0] = fma2(xv1, wA.x, acc1[0]);
                acc0[1] = fma2(xv0, wA.y, acc0[1]);  acc1[1] = fma2(xv1, wA.y, acc1[1]);
                acc0[2] = fma2(xv0, wB.x, acc0[2]);  acc1[2] = fma2(xv1, wB.x, acc1[2]);
                acc0[3] = fma2(xv0, wB.y, acc0[3]);  acc1[3] = fma2(xv1, wB.y, acc1[3]);
                acc0[4] = fma2(xv0, wC.x, acc0[4]);  acc1[4] = fma2(xv1, wC.x, acc1[4]);
                acc0[5] = fma2(xv0, wC.y, acc0[5]);  acc1[5] = fma2(xv1, wC.y, acc1[5]);
                acc0[6] = fma2(xv0, wD.x, acc0[6]);  acc1[6] = fma2(xv1, wD.x, acc1[6]);
                acc0[7] = fma2(xv0, wD.y, acc0[7]);  acc1[7] = fma2(xv1, wD.y, acc1[7]);
            }
        }
    }

    int i0 = gr0 + lane;
    int i1 = i0 + 32;
    if (i0 < n) {
        unsigned long long* yo = reinterpret_cast<unsigned long long*>(g_y + (size_t)i0 * 16);
#pragma unroll
        for (int j = 0; j < 8; j++) yo[j] = acc0[j];
    }
    if (i1 < n) {
        unsigned long long* yo = reinterpret_cast<unsigned long long*>(g_y + (size_t)i1 * 16);
#pragma unroll
        for (int j = 0; j < 8; j++) yo[j] = acc1[j];
    }
}

// ---------------------------------------------------------------------------
// K3: y'[i] = y[i] * rsqrt(cnt[i]+1) (in-place). One float4 per thread.
// Thread 0 snapshots + resets the overflow counter for this call.
__global__ void k_scale(int n) {
    int i = blockIdx.x * blockDim.x + threadIdx.x;   // over n*4 float4s
    if (blockIdx.x == 0 && threadIdx.x == 0) {
        g_ovf_cnt2 = g_ovf_cnt;
        g_ovf_cnt = 0;
    }
    if (i >= n * 4) return;
    float d = rsqrtf((float)(g_cnt[i >> 2] + 1));
    float4* p = reinterpret_cast<float4*>(g_y) + i;
    float4 v = *p;
    v.x *= d; v.y *= d; v.z *= d; v.w *= d;
    *p = v;
}

// ---------------------------------------------------------------------------
// K4: gather-aggregate over pre-scaled y'. One warp per node. Lane layout:
// sub = lane>>2 (entry slot 0..7), q = lane&3 (feature quad). Branch-free:
// loads issued unconditionally for full 16-entry chunks (bucket slots < CAP
// always hold valid-or-stale node ids < n; max index 127 < CAP), adds are
// lane-predicated. Two independent gather chains per iteration.
__global__ void k_agg(int n) {
    int warp = (blockIdx.x * blockDim.x + threadIdx.x) >> 5;
    int lane = threadIdx.x & 31;
    if (warp >= n) return;
    int c   = warp;
    int sub = lane >> 2;
    int q   = lane & 3;

    int cnt = g_cnt[c];
    int m   = cnt < CAP ? cnt : CAP;
    const int* bk = g_bucket + (size_t)c * CAP;
    const char* yb = reinterpret_cast<const char*>(g_y) + (q << 4);  // per-lane base

    float4 accA = make_float4(0.f, 0.f, 0.f, 0.f);
    float4 accB = make_float4(0.f, 0.f, 0.f, 0.f);

    for (int k = 0; k < m; k += 16) {
        int e0 = k + sub;            // <= 119
        int e1 = k + 8 + sub;        // <= 127 (< CAP, always safe to read)
        int r0 = __ldg(bk + e0);
        int r1 = __ldg(bk + e1);
        float4 v0 = *reinterpret_cast<const float4*>(yb + ((size_t)(unsigned)r0 << 6));
        float4 v1 = *reinterpret_cast<const float4*>(yb + ((size_t)(unsigned)r1 << 6));
        if (e0 < m) { accA.x += v0.x; accA.y += v0.y; accA.z += v0.z; accA.w += v0.w; }
        if (e1 < m) { accB.x += v1.x; accB.y += v1.y; accB.z += v1.z; accB.w += v1.w; }
    }
    accA.x += accB.x; accA.y += accB.y; accA.z += accB.z; accA.w += accB.w;

    if (cnt > CAP && lane < 4) {  // rare/adversarial: scan overflow snapshot
        int oc = g_ovf_cnt2; if (oc > EMAX) oc = EMAX;
        for (int i = 0; i < oc; i++)
            if (g_ovf_c[i] == c) {
                float4 v = *reinterpret_cast<const float4*>(
                    g_y + (((unsigned)g_ovf_r[i]) << 4) + (lane << 2));
                accA.x += v.x; accA.y += v.y; accA.z += v.z; accA.w += v.w;
            }
    }

#pragma unroll
    for (int off = 4; off <= 16; off <<= 1) {
        accA.x += __shfl_xor_sync(0xffffffff, accA.x, off);
        accA.y += __shfl_xor_sync(0xffffffff, accA.y, off);
        accA.z += __shfl_xor_sync(0xffffffff, accA.z, off);
        accA.w += __shfl_xor_sync(0xffffffff, accA.w, off);
    }

    if (lane < 4) {
        float dc = rsqrtf((float)(cnt + 1));
        float4 self = *reinterpret_cast<const float4*>(g_y + (((unsigned)c) << 4) + (lane << 2));
        float4 o;
        o.x = (accA.x + self.x) * dc;
        o.y = (accA.y + self.y) * dc;
        o.z = (accA.z + self.z) * dc;
        o.w = (accA.w + self.w) * dc;
        *reinterpret_cast<float4*>(g_acc + (((unsigned)c) << 4) + (lane << 2)) = o;
    }
    if (lane == 0) g_cnt[c] = 0;   // self-clean for next replay
}

// ---------------------------------------------------------------------------
// K5: finalize: h0 = relu(acc + bg); 3-layer MLP + sigmoid. One node/thread.
__global__ void k_final(const float* __restrict__ bg,
                        const float* __restrict__ W1, const float* __restrict__ b1,
                        const float* __restrict__ W2, const float* __restrict__ b2,
                        const float* __restrict__ W3, const float* __restrict__ b3,
                        float* __restrict__ out, int n) {
    __shared__ float sW1[256], sW2[512], sW3[32];
    __shared__ float sbg[16], sb1[16], sb2[32], sb3;
    int t = threadIdx.x;
    if (t < 256) sW1[t] = W1[t];
    for (int q = t; q < 512; q += blockDim.x) sW2[q] = W2[q];
    if (t < 32) { sW3[t] = W3[t]; sb2[t] = b2[t]; }
    if (t < 16) { sb1[t] = b1[t]; sbg[t] = bg[t]; }
    if (t == 0) sb3 = b3[0];
    __syncthreads();

    int i = blockIdx.x * blockDim.x + t;
    if (i >= n) return;

    const float4* ar = reinterpret_cast<const float4*>(g_acc) + (size_t)i * 4;

    float h0[16];
#pragma unroll
    for (int q = 0; q < 4; q++) {
        float4 a = ar[q];
        h0[q * 4 + 0] = fmaxf(a.x + sbg[q * 4 + 0], 0.f);
        h0[q * 4 + 1] = fmaxf(a.y + sbg[q * 4 + 1], 0.f);
        h0[q * 4 + 2] = fmaxf(a.z + sbg[q * 4 + 2], 0.f);
        h0[q * 4 + 3] = fmaxf(a.w + sbg[q * 4 + 3], 0.f);
    }

    float h1[16];
#pragma unroll
    for (int j = 0; j < 16; j++) {
        float s = sb1[j];
#pragma unroll
        for (int k = 0; k < 16; k++) s += h0[k] * sW1[k * 16 + j];
        h1[j] = fmaxf(s, 0.f);
    }

    float z = sb3;
#pragma unroll
    for (int j = 0; j < 32; j++) {
        float s = sb2[j];
#pragma unroll
        for (int k = 0; k < 16; k++) s += h1[k] * sW2[k * 32 + j];
        z += fmaxf(s, 0.f) * sW3[j];
    }

    out[i] = 1.f / (1.f + expf(-z));
}

// ---------------------------------------------------------------------------
extern "C" void kernel_launch(void* const* d_in, const int* in_sizes, int n_in,
                              void* d_out, int out_size) {
    const float* x  = (const float*)d_in[0];
    const int*   ei = (const int*)d_in[1];   // edge_index words (int32 or int64 LE)
    const float* Wg = (const float*)d_in[2];
    const float* bg = (const float*)d_in[3];
    const float* W1 = (const float*)d_in[4];
    const float* b1 = (const float*)d_in[5];
    const float* W2 = (const float*)d_in[6];
    const float* b2 = (const float*)d_in[7];
    const float* W3 = (const float*)d_in[8];
    const float* b3 = (const float*)d_in[9];
    float* out = (float*)d_out;

    int n = in_sizes[0] / 512;
    int E = in_sizes[1] / 2;   // element count, dtype-independent
    if (n > NMAX) n = NMAX;
    if (E > EMAX) E = EMAX;

    // One-time setup on the eager correctness call (NOT during capture).
    static int inited = 0;
    static cudaStream_t s2;
    static cudaEvent_t evFork, evGemm;
    int gemm_smem = (512 * 16 + NSTG * NPB * KC) * 4;  // 64KB
    if (!inited) {
        cudaFuncSetAttribute(k_gemm, cudaFuncAttributeMaxDynamicSharedMemorySize, gemm_smem);
        cudaStreamCreateWithFlags(&s2, cudaStreamNonBlocking);
        cudaEventCreateWithFlags(&evFork, cudaEventDisableTiming);
        cudaEventCreateWithFlags(&evGemm, cudaEventDisableTiming);
        inited = 1;
    }

    // Fork: gemm (x@Wg) is independent of the edge pipeline -> run on s2.
    cudaEventRecord(evFork, 0);
    cudaStreamWaitEvent(s2, evFork, 0);
    k_gemm<<<(n + NPB - 1) / NPB, BLK, gemm_smem, s2>>>(x, Wg, n);
    cudaEventRecord(evGemm, s2);

    // Edge arm on the capture (NULL) stream: just the bucket fill now.
    k_fill<<<(E + 255) / 256, 256>>>(ei, E, n);

    // Join, then scale y by dinv (needs both arms), gather, MLP.
    cudaStreamWaitEvent(0, evGemm, 0);
    k_scale<<<(n * 4 + 255) / 256, 256>>>(n);
    k_agg  <<<(n * 32 + 255) / 256, 256>>>(n);
    k_final<<<(n + 255) / 256, 256>>>(bg, W1, b1, W2, b2, W3, b3, out, n);
}